// round 15
// baseline (speedup 1.0000x reference)
#include <cuda_runtime.h>
#include <cmath>

#define TL 512
#define WN 16
#define HD 64
#define DM 512
#define ATT_SZ (1024*DM)
#define PP_SZ  (1024*896)
#define Y_SZ   (1024*DM)

#define INV2PI 0.15915494309189535f
#define MAGIC  12582912.0f
#define C2PI_A 6.2831854820251465f

typedef unsigned long long u64;
typedef unsigned int u32;

// ---------------- static scratch (no allocation) ---------------------------
__device__ float g_freq [16*TL*WN];
__device__ float g_phase[16*TL*WN];
__device__ float g_amp  [16*TL*WN];
__device__ float g_v    [16*TL*HD];
__device__ float g_att8 [8*ATT_SZ];   // attn@V partials, slot = k-tile index
__device__ float g_pp   [2*PP_SZ];    // proj partials, [z][m][896]
__device__ float g_y4   [4*Y_SZ];     // outproj partials, [z][m][512]

// ---------------- f32x2 packed helpers -------------------------------------
__device__ __forceinline__ u64 pk2(float x, float y) {
    u64 r;
    asm("mov.b64 %0, {%1, %2};" : "=l"(r)
        : "r"(__float_as_uint(x)), "r"(__float_as_uint(y)));
    return r;
}
__device__ __forceinline__ u64 dup2(float x) { return pk2(x, x); }
__device__ __forceinline__ void up2(u64 v, float& x, float& y) {
    unsigned a, b;
    asm("mov.b64 {%0, %1}, %2;" : "=r"(a), "=r"(b) : "l"(v));
    x = __uint_as_float(a); y = __uint_as_float(b);
}
__device__ __forceinline__ u64 f2fma(u64 a, u64 b, u64 c) {
    u64 d; asm("fma.rn.f32x2 %0, %1, %2, %3;" : "=l"(d) : "l"(a), "l"(b), "l"(c));
    return d;
}
__device__ __forceinline__ u64 f2add(u64 a, u64 b) {
    u64 d; asm("add.rn.f32x2 %0, %1, %2;" : "=l"(d) : "l"(a), "l"(b));
    return d;
}
__device__ __forceinline__ u64 f2mul(u64 a, u64 b) {
    u64 d; asm("mul.rn.f32x2 %0, %1, %2;" : "=l"(d) : "l"(a), "l"(b));
    return d;
}
__device__ __forceinline__ void mm4x4(const float4& a4, const ulonglong2& bb,
                                      u64 acc2[4][2]) {
    u64 t;
    t = dup2(a4.x); acc2[0][0] = f2fma(t, bb.x, acc2[0][0]);
                    acc2[0][1] = f2fma(t, bb.y, acc2[0][1]);
    t = dup2(a4.y); acc2[1][0] = f2fma(t, bb.x, acc2[1][0]);
                    acc2[1][1] = f2fma(t, bb.y, acc2[1][1]);
    t = dup2(a4.z); acc2[2][0] = f2fma(t, bb.x, acc2[2][0]);
                    acc2[2][1] = f2fma(t, bb.y, acc2[2][1]);
    t = dup2(a4.w); acc2[3][0] = f2fma(t, bb.x, acc2[3][0]);
                    acc2[3][1] = f2fma(t, bb.y, acc2[3][1]);
}

// ---------------- GEMM core: k-range, 64x64 tile, depth-2 reg pipeline -----
__device__ __forceinline__ void gemm64k(const float* __restrict__ A,
                                        const float* __restrict__ W, int ldw,
                                        int m0, int n0, int kbeg, int kend,
                                        u64 acc2[4][2])
{
    __shared__ float As[2][16][68];
    __shared__ float Ws[2][16][68];
    const int tid = threadIdx.x;
    const int lm  = tid >> 2;
    const int lk4 = (tid & 3) << 2;
    const int lkk = tid >> 4;
    const int ln4 = (tid & 15) << 2;
    const int tx  = tid & 15;
    const int ty  = tid >> 4;

    const float* Ar = A + (size_t)(m0 + lm) * DM + lk4;
    const float* Wb = W + (size_t)lkk * ldw + n0 + ln4;

    // depth-2 prefetch: a0/w0 = chunk k0, a1/w1 = chunk k0+16
    float4 a0 = *(const float4*)(Ar + kbeg);
    float4 w0 = *(const float4*)(Wb + (size_t)kbeg * ldw);
    float4 a1 = *(const float4*)(Ar + kbeg + 16);
    float4 w1 = *(const float4*)(Wb + (size_t)(kbeg + 16) * ldw);

    int buf = 0;
#pragma unroll 1
    for (int k0 = kbeg; k0 < kend; k0 += 16) {
        As[buf][lk4 + 0][lm] = a0.x;
        As[buf][lk4 + 1][lm] = a0.y;
        As[buf][lk4 + 2][lm] = a0.z;
        As[buf][lk4 + 3][lm] = a0.w;
        *(float4*)&Ws[buf][lkk][ln4] = w0;
        __syncthreads();
        a0 = a1; w0 = w1;
        if (k0 + 32 < kend) {          // issue chunk k0+32 (consumed 2 iters out)
            a1 = *(const float4*)(Ar + k0 + 32);
            w1 = *(const float4*)(Wb + (size_t)(k0 + 32) * ldw);
        }
#pragma unroll
        for (int kk = 0; kk < 16; kk++) {
            float4 a4 = *(const float4*)&As[buf][kk][ty << 2];
            ulonglong2 bb = *(const ulonglong2*)&Ws[buf][kk][tx << 2];
            mm4x4(a4, bb, acc2);
        }
        buf ^= 1;
    }
}

// ---------------- stage 1a: projection GEMM, split-K=2, 448 CTAs -----------
__global__ __launch_bounds__(256, 3)
void proj_split(const float* __restrict__ x,
                const float* __restrict__ Wf, const float* __restrict__ Wp,
                const float* __restrict__ Wa, const float* __restrict__ Wv)
{
    const int nt = blockIdx.x;
    const int m0 = blockIdx.y * 64;
    const int z  = blockIdx.z;
    const float* W; int ldw, nc0;
    if      (nt < 2) { W = Wf; ldw = 128; nc0 = nt*64;       }
    else if (nt < 4) { W = Wp; ldw = 128; nc0 = nt*64 - 128; }
    else if (nt < 6) { W = Wa; ldw = 128; nc0 = nt*64 - 256; }
    else             { W = Wv; ldw = 512; nc0 = nt*64 - 384; }

    u64 acc2[4][2] = {};
    gemm64k(x, W, ldw, m0, nc0, z * 256, z * 256 + 256, acc2);

    float* dst = g_pp + (size_t)z * PP_SZ;
    const int tx = threadIdx.x & 15, ty = threadIdx.x >> 4;
    const int gcol = nt * 64 + (tx << 2);
#pragma unroll
    for (int i = 0; i < 4; i++) {
        float c0, c1, c2, c3;
        up2(acc2[i][0], c0, c1);
        up2(acc2[i][1], c2, c3);
        int m = m0 + (ty << 2) + i;
        *(float4*)&dst[(size_t)m * 896 + gcol] = make_float4(c0, c1, c2, c3);
    }
}

// ---------------- stage 1b: reduce + bias + softplus + scatter -------------
__global__ __launch_bounds__(224)
void projred(const float* __restrict__ bf, const float* __restrict__ bp,
             const float* __restrict__ ba, const float* __restrict__ bv)
{
    const int m   = blockIdx.x;
    const int col = threadIdx.x * 4;
    const size_t off = (size_t)m * 896 + col;
    float4 p0 = *(const float4*)(g_pp + off);
    float4 p1 = *(const float4*)(g_pp + PP_SZ + off);
    const int b = m >> 9, t = m & 511;

    const float* bias; int lc; int kind;
    if      (col < 128) { bias = bf; lc = col;       kind = 0; }
    else if (col < 256) { bias = bp; lc = col - 128; kind = 1; }
    else if (col < 384) { bias = ba; lc = col - 256; kind = 2; }
    else                { bias = bv; lc = col - 384; kind = 3; }

    float4 bb = *(const float4*)(bias + lc);
    float v0 = (p0.x + p1.x) + bb.x;
    float v1 = (p0.y + p1.y) + bb.y;
    float v2 = (p0.z + p1.z) + bb.z;
    float v3 = (p0.w + p1.w) + bb.w;

    if (kind == 2) {
        v0 = fmaxf(v0, 0.f) + log1pf(expf(-fabsf(v0))) + 1e-8f;
        v1 = fmaxf(v1, 0.f) + log1pf(expf(-fabsf(v1))) + 1e-8f;
        v2 = fmaxf(v2, 0.f) + log1pf(expf(-fabsf(v2))) + 1e-8f;
        v3 = fmaxf(v3, 0.f) + log1pf(expf(-fabsf(v3))) + 1e-8f;
    }
    float4 out = make_float4(v0, v1, v2, v3);

    if (kind < 3) {
        int h = lc >> 4, w = lc & 15;
        float* dstb = (kind == 0) ? g_freq : (kind == 1) ? g_phase : g_amp;
        *(float4*)&dstb[(((size_t)(b*8 + h) * TL) + t) * WN + w] = out;
    } else {
        int h = lc >> 6, d = lc & 63;
        *(float4*)&g_v[(((size_t)(b*8 + h) * TL) + t) * HD + d] = out;
    }
}

// ---------------- stage 2: attention, ONE causal tile per CTA --------------
// grid (16 bh, 36 tiles): tile id -> (qt, kti) triangular decode; 576 CTAs
__global__ __launch_bounds__(256, 2)
void attn_tile()
{
    __shared__ float s_fpa[64 * 52];
    __shared__ float s_s2p[64 * 4];
    __shared__ float s_att[64 * 68];
    __shared__ float s_v  [64 * 68];

    const int bh = blockIdx.x;
    // triangular decode: by -> (qt, kti), kti <= qt
    int by = blockIdx.y;
    int qt = (int)((sqrtf((float)(8 * by + 1)) - 1.0f) * 0.5f);
    int tri = (qt * (qt + 1)) >> 1;
    if (by < tri)               { qt--; tri = (qt * (qt + 1)) >> 1; }
    else if (by >= tri + qt + 1){ qt++; tri = (qt * (qt + 1)) >> 1; }
    const int kti = by - tri;
    const int kt  = kti * 64;

    const int tid = threadIdx.x;
    const int qa = tid >> 2;
    const int g  = tid & 3;
    const int ty = tid >> 4;
    const int tx = tid & 15;
    const int qglob = qt * 64 + qa;
    const int b = bh >> 3, h = bh & 7;

    // q-side params in packed registers
    u64 fq2[8], pq2[8], aq2[8];
    {
        const ulonglong2* f2 = (const ulonglong2*)(g_freq  + (((size_t)bh*TL) + qglob) * WN);
        const ulonglong2* p2 = (const ulonglong2*)(g_phase + (((size_t)bh*TL) + qglob) * WN);
        const ulonglong2* a2 = (const ulonglong2*)(g_amp   + (((size_t)bh*TL) + qglob) * WN);
#pragma unroll
        for (int i = 0; i < 4; i++) {
            ulonglong2 t;
            t = f2[i]; fq2[2*i] = t.x; fq2[2*i+1] = t.y;
            t = p2[i]; pq2[2*i] = t.x; pq2[2*i+1] = t.y;
            t = a2[i]; aq2[2*i] = t.x; aq2[2*i+1] = t.y;
        }
    }
    float s2q;
    {
        u64 s2 = 0ull;
#pragma unroll
        for (int i = 0; i < 8; i++) s2 = f2fma(aq2[i], aq2[i], s2);
        float lo, hi; up2(s2, lo, hi); s2q = lo + hi;
    }

    const u64 inv2pi2 = dup2(INV2PI);
    const u64 magic2  = dup2(MAGIC);
    const u64 nmagic2 = dup2(-MAGIC);
    const u64 nc2pi2  = dup2(-C2PI_A);

    // ---- stage k-tile: negated f/p, amp, per-row a^2 partials, V ----
    {
        int row = tid >> 2, c4 = (tid & 3) << 2;
        size_t base = ((size_t)bh * TL + (kt + row)) * WN + c4;
        float4 f = *(const float4*)(g_freq  + base);
        float4 p = *(const float4*)(g_phase + base);
        float4 a = *(const float4*)(g_amp   + base);
        *(float4*)&s_fpa[row*52 +      c4] = make_float4(-f.x, -f.y, -f.z, -f.w);
        *(float4*)&s_fpa[row*52 + 16 + c4] = make_float4(-p.x, -p.y, -p.z, -p.w);
        *(float4*)&s_fpa[row*52 + 32 + c4] = a;
        s_s2p[row*4 + (tid & 3)] = a.x*a.x + a.y*a.y + a.z*a.z + a.w*a.w;
#pragma unroll
        for (int i = 0; i < 4; i++) {
            int l = tid + i * 256;
            int r = l >> 4, cc = (l & 15) << 2;
            *(float4*)&s_v[r*68 + cc] =
                *(const float4*)(g_v + ((size_t)bh*TL + (kt + r)) * HD + cc);
        }
    }
    __syncthreads();

    // ---- phase A: attn tile (f32x2 wave pairs) ----
#pragma unroll 1
    for (int j = 0; j < 16; j++) {
        int kl = g + (j << 2);
        int kg = kt + kl;
        float attv = 0.f;
        if (kg <= qglob) {
            const float dtv = (float)(qglob - kg);
            const u64 dt2 = dup2(dtv);
            const float* fk = &s_fpa[kl * 52];
            float4 s2p = *(const float4*)&s_s2p[kl * 4];
            float s2k = (s2p.x + s2p.y) + (s2p.z + s2p.w);
            u64 cacc2 = 0ull, dacc2 = 0ull;
#pragma unroll
            for (int g4 = 0; g4 < 4; g4++) {
                ulonglong2 nf = *(const ulonglong2*)(fk +      (g4 << 2));
                ulonglong2 np = *(const ulonglong2*)(fk + 16 + (g4 << 2));
                ulonglong2 aa = *(const ulonglong2*)(fk + 32 + (g4 << 2));
#pragma unroll
                for (int half = 0; half < 2; half++) {
                    int wp = 2*g4 + half;
                    u64 nfp = half ? nf.y : nf.x;
                    u64 npp = half ? np.y : np.x;
                    u64 aap = half ? aa.y : aa.x;
                    u64 dw  = f2add(fq2[wp], nfp);
                    u64 dp  = f2add(pq2[wp], npp);
                    u64 arg = f2fma(dw, dt2, dp);
                    u64 tr  = f2fma(arg, inv2pi2, magic2);
                    u64 nn  = f2add(tr, nmagic2);
                    u64 rr  = f2fma(nn, nc2pi2, arg);
                    float r0, r1; up2(rr, r0, r1);
                    u64 cs  = pk2(__cosf(r0), __cosf(r1));
                    u64 pp  = f2mul(aq2[wp], aap);
                    dacc2 = f2add(dacc2, pp);
                    cacc2 = f2fma(pp, cs, cacc2);
                }
            }
            float c0, c1, d0, d1;
            up2(cacc2, c0, c1); up2(dacc2, d0, d1);
            float cacc = c0 + c1, dacc = d0 + d1;
            float S  = s2q + s2k;
            float it = fmaf(2.f, cacc, S);
            float en = fmaf(2.f, dacc, S) + 1e-8f;
            attv = __fdividef(it, en);
        }
        s_att[kl * 68 + qa] = attv;
    }
    __syncthreads();

    // ---- phase B: acc = attn_tile @ V_tile (f32x2) ----
    u64 acc2[4][2] = {};
#pragma unroll 4
    for (int kk = 0; kk < 64; kk++) {
        float4 a4 = *(const float4*)&s_att[kk*68 + (ty << 2)];
        ulonglong2 vv = *(const ulonglong2*)&s_v[kk*68 + (tx << 2)];
        mm4x4(a4, vv, acc2);
    }

    // ---- epilogue: write tile to slot kti ----
    float* dst = g_att8 + (size_t)kti * ATT_SZ;
#pragma unroll
    for (int i = 0; i < 4; i++) {
        float c0, c1, c2, c3;
        up2(acc2[i][0], c0, c1);
        up2(acc2[i][1], c2, c3);
        int row = qt * 64 + (ty << 2) + i;
        *(float4*)&dst[((size_t)(b * TL + row)) * DM + h * HD + (tx << 2)] =
            make_float4(c0, c1, c2, c3);
    }
}

// ---------------- stage 2b: reduce live slots 1..qt into slot 0 ------------
// grid 1024 rows, 128 threads (one float4 per thread across 512 cols)
__global__ __launch_bounds__(128)
void attred()
{
    const int m   = blockIdx.x;
    const int col = threadIdx.x * 4;
    const int nsum = ((m & 511) >> 6) + 1;       // live slots for this row
    const size_t off = (size_t)m * DM + col;

    ulonglong2 acc = *(const ulonglong2*)(g_att8 + off);
#pragma unroll
    for (int jb = 1; jb < 8; jb++) {
        if (jb < nsum) {
            ulonglong2 t = *(const ulonglong2*)(g_att8 + (size_t)jb * ATT_SZ + off);
            acc.x = f2add(acc.x, t.x);
            acc.y = f2add(acc.y, t.y);
        }
    }
    *(ulonglong2*)(g_att8 + off) = acc;
}

// ---------------- stage 3a: output projection, split-K=4, single-A ---------
// grid (8 n-tiles, 16 m-tiles, 4 z); K=128 each; A = g_att8 slot 0
__global__ __launch_bounds__(256, 3)
void outp_split4(const float* __restrict__ Wo)
{
    const int n0 = blockIdx.x * 64;
    const int m0 = blockIdx.y * 64;
    const int z  = blockIdx.z;
    u64 acc2[4][2] = {};
    gemm64k(g_att8, Wo, DM, m0, n0, z * 128, z * 128 + 128, acc2);

    float* dst = g_y4 + (size_t)z * Y_SZ;
    const int tx = threadIdx.x & 15, ty = threadIdx.x >> 4;
#pragma unroll
    for (int i = 0; i < 4; i++) {
        float c0, c1, c2, c3;
        up2(acc2[i][0], c0, c1);
        up2(acc2[i][1], c2, c3);
        int m = m0 + (ty << 2) + i;
        *(float4*)&dst[(size_t)m * DM + n0 + (tx << 2)] =
            make_float4(c0, c1, c2, c3);
    }
}

// ---------------- stage 3b: y = sum(4 partials) + bias ----------------------
__global__ __launch_bounds__(256)
void yred(const float* __restrict__ bo, float* __restrict__ y)
{
    int i = blockIdx.x * 256 + threadIdx.x;      // float4 index, 131072 total
    float4 p0 = ((const float4*)(g_y4 + 0*Y_SZ))[i];
    float4 p1 = ((const float4*)(g_y4 + 1*Y_SZ))[i];
    float4 p2 = ((const float4*)(g_y4 + 2*Y_SZ))[i];
    float4 p3 = ((const float4*)(g_y4 + 3*Y_SZ))[i];
    int col = (i << 2) & 511;
    float4 bb = *(const float4*)(bo + col);
    ((float4*)y)[i] = make_float4(
        ((p0.x + p1.x) + (p2.x + p3.x)) + bb.x,
        ((p0.y + p1.y) + (p2.y + p3.y)) + bb.y,
        ((p0.z + p1.z) + (p2.z + p3.z)) + bb.z,
        ((p0.w + p1.w) + (p2.w + p3.w)) + bb.w);
}

// ---------------- launch ----------------------------------------------------
extern "C" void kernel_launch(void* const* d_in, const int* in_sizes, int n_in,
                              void* d_out, int out_size)
{
    const float* x  = (const float*)d_in[0];
    const float* Wf = (const float*)d_in[1];
    const float* bf = (const float*)d_in[2];
    const float* Wp = (const float*)d_in[3];
    const float* bp = (const float*)d_in[4];
    const float* Wa = (const float*)d_in[5];
    const float* ba = (const float*)d_in[6];
    const float* Wv = (const float*)d_in[7];
    const float* bv = (const float*)d_in[8];
    const float* Wo = (const float*)d_in[9];
    const float* bo = (const float*)d_in[10];
    float* y = (float*)d_out;

    proj_split<<<dim3(14, 16, 2), 256>>>(x, Wf, Wp, Wa, Wv);
    projred<<<1024, 224>>>(bf, bp, ba, bv);
    attn_tile<<<dim3(16, 36), 256>>>();
    attred<<<1024, 128>>>();
    outp_split4<<<dim3(8, 16, 4), 256>>>(Wo);
    yred<<<512, 256>>>(bo, y);
}

// round 16
// speedup vs baseline: 1.0424x; 1.0424x over previous
#include <cuda_runtime.h>
#include <cmath>

#define TL 512
#define WN 16
#define HD 64
#define DM 512
#define ATT_SZ (1024*DM)
#define PP_SZ  (1024*896)
#define Y_SZ   (1024*DM)

typedef unsigned long long u64;
typedef unsigned int u32;

// ---------------- static scratch (no allocation) ---------------------------
__device__ float g_freq [16*TL*WN];
__device__ float g_phase[16*TL*WN];
__device__ float g_amp  [16*TL*WN];
__device__ float g_v    [16*TL*HD];
__device__ float g_att8 [8*ATT_SZ];   // attn@V partials, slot = k-tile index
__device__ float g_pp   [2*PP_SZ];    // proj partials, [z][m][896]
__device__ float g_y4   [4*Y_SZ];     // outproj partials, [z][m][512]

// ---------------- f32x2 packed helpers -------------------------------------
__device__ __forceinline__ u64 pk2(float x, float y) {
    u64 r;
    asm("mov.b64 %0, {%1, %2};" : "=l"(r)
        : "r"(__float_as_uint(x)), "r"(__float_as_uint(y)));
    return r;
}
__device__ __forceinline__ u64 dup2(float x) { return pk2(x, x); }
__device__ __forceinline__ void up2(u64 v, float& x, float& y) {
    unsigned a, b;
    asm("mov.b64 {%0, %1}, %2;" : "=r"(a), "=r"(b) : "l"(v));
    x = __uint_as_float(a); y = __uint_as_float(b);
}
__device__ __forceinline__ u64 f2fma(u64 a, u64 b, u64 c) {
    u64 d; asm("fma.rn.f32x2 %0, %1, %2, %3;" : "=l"(d) : "l"(a), "l"(b), "l"(c));
    return d;
}
__device__ __forceinline__ u64 f2add(u64 a, u64 b) {
    u64 d; asm("add.rn.f32x2 %0, %1, %2;" : "=l"(d) : "l"(a), "l"(b));
    return d;
}
__device__ __forceinline__ u64 f2mul(u64 a, u64 b) {
    u64 d; asm("mul.rn.f32x2 %0, %1, %2;" : "=l"(d) : "l"(a), "l"(b));
    return d;
}
__device__ __forceinline__ void mm4x4(const float4& a4, const ulonglong2& bb,
                                      u64 acc2[4][2]) {
    u64 t;
    t = dup2(a4.x); acc2[0][0] = f2fma(t, bb.x, acc2[0][0]);
                    acc2[0][1] = f2fma(t, bb.y, acc2[0][1]);
    t = dup2(a4.y); acc2[1][0] = f2fma(t, bb.x, acc2[1][0]);
                    acc2[1][1] = f2fma(t, bb.y, acc2[1][1]);
    t = dup2(a4.z); acc2[2][0] = f2fma(t, bb.x, acc2[2][0]);
                    acc2[2][1] = f2fma(t, bb.y, acc2[2][1]);
    t = dup2(a4.w); acc2[3][0] = f2fma(t, bb.x, acc2[3][0]);
                    acc2[3][1] = f2fma(t, bb.y, acc2[3][1]);
}

// ---------------- GEMM core: k-range, 64x64 tile, depth-1 (R14) ------------
__device__ __forceinline__ void gemm64k(const float* __restrict__ A,
                                        const float* __restrict__ W, int ldw,
                                        int m0, int n0, int kbeg, int kend,
                                        u64 acc2[4][2])
{
    __shared__ float As[2][16][68];
    __shared__ float Ws[2][16][68];
    const int tid = threadIdx.x;
    const int lm  = tid >> 2;
    const int lk4 = (tid & 3) << 2;
    const int lkk = tid >> 4;
    const int ln4 = (tid & 15) << 2;
    const int tx  = tid & 15;
    const int ty  = tid >> 4;

    const float* Ar = A + (size_t)(m0 + lm) * DM + lk4;
    const float* Wb = W + (size_t)lkk * ldw + n0 + ln4;

    float4 a = *(const float4*)(Ar + kbeg);
    float4 w = *(const float4*)(Wb + (size_t)kbeg * ldw);

    int buf = 0;
#pragma unroll 1
    for (int k0 = kbeg; k0 < kend; k0 += 16) {
        As[buf][lk4 + 0][lm] = a.x;
        As[buf][lk4 + 1][lm] = a.y;
        As[buf][lk4 + 2][lm] = a.z;
        As[buf][lk4 + 3][lm] = a.w;
        *(float4*)&Ws[buf][lkk][ln4] = w;
        __syncthreads();
        if (k0 + 16 < kend) {
            a = *(const float4*)(Ar + k0 + 16);
            w = *(const float4*)(Wb + (size_t)(k0 + 16) * ldw);
        }
#pragma unroll
        for (int kk = 0; kk < 16; kk++) {
            float4 a4 = *(const float4*)&As[buf][kk][ty << 2];
            ulonglong2 bb = *(const ulonglong2*)&Ws[buf][kk][tx << 2];
            mm4x4(a4, bb, acc2);
        }
        buf ^= 1;
    }
}

// ---------------- stage 1a: projection GEMM, split-K=2, 448 CTAs -----------
__global__ __launch_bounds__(256, 3)
void proj_split(const float* __restrict__ x,
                const float* __restrict__ Wf, const float* __restrict__ Wp,
                const float* __restrict__ Wa, const float* __restrict__ Wv)
{
    const int nt = blockIdx.x;
    const int m0 = blockIdx.y * 64;
    const int z  = blockIdx.z;
    const float* W; int ldw, nc0;
    if      (nt < 2) { W = Wf; ldw = 128; nc0 = nt*64;       }
    else if (nt < 4) { W = Wp; ldw = 128; nc0 = nt*64 - 128; }
    else if (nt < 6) { W = Wa; ldw = 128; nc0 = nt*64 - 256; }
    else             { W = Wv; ldw = 512; nc0 = nt*64 - 384; }

    u64 acc2[4][2] = {};
    gemm64k(x, W, ldw, m0, nc0, z * 256, z * 256 + 256, acc2);

    float* dst = g_pp + (size_t)z * PP_SZ;
    const int tx = threadIdx.x & 15, ty = threadIdx.x >> 4;
    const int gcol = nt * 64 + (tx << 2);
#pragma unroll
    for (int i = 0; i < 4; i++) {
        float c0, c1, c2, c3;
        up2(acc2[i][0], c0, c1);
        up2(acc2[i][1], c2, c3);
        int m = m0 + (ty << 2) + i;
        *(float4*)&dst[(size_t)m * 896 + gcol] = make_float4(c0, c1, c2, c3);
    }
}

// ---------------- stage 1b: reduce + bias + softplus + scatter -------------
__global__ __launch_bounds__(224)
void projred(const float* __restrict__ bf, const float* __restrict__ bp,
             const float* __restrict__ ba, const float* __restrict__ bv)
{
    const int m   = blockIdx.x;
    const int col = threadIdx.x * 4;
    const size_t off = (size_t)m * 896 + col;
    float4 p0 = *(const float4*)(g_pp + off);
    float4 p1 = *(const float4*)(g_pp + PP_SZ + off);
    const int b = m >> 9, t = m & 511;

    const float* bias; int lc; int kind;
    if      (col < 128) { bias = bf; lc = col;       kind = 0; }
    else if (col < 256) { bias = bp; lc = col - 128; kind = 1; }
    else if (col < 384) { bias = ba; lc = col - 256; kind = 2; }
    else                { bias = bv; lc = col - 384; kind = 3; }

    float4 bb = *(const float4*)(bias + lc);
    float v0 = (p0.x + p1.x) + bb.x;
    float v1 = (p0.y + p1.y) + bb.y;
    float v2 = (p0.z + p1.z) + bb.z;
    float v3 = (p0.w + p1.w) + bb.w;

    if (kind == 2) {
        v0 = fmaxf(v0, 0.f) + log1pf(expf(-fabsf(v0))) + 1e-8f;
        v1 = fmaxf(v1, 0.f) + log1pf(expf(-fabsf(v1))) + 1e-8f;
        v2 = fmaxf(v2, 0.f) + log1pf(expf(-fabsf(v2))) + 1e-8f;
        v3 = fmaxf(v3, 0.f) + log1pf(expf(-fabsf(v3))) + 1e-8f;
    }
    float4 out = make_float4(v0, v1, v2, v3);

    if (kind < 3) {
        int h = lc >> 4, w = lc & 15;
        float* dstb = (kind == 0) ? g_freq : (kind == 1) ? g_phase : g_amp;
        *(float4*)&dstb[(((size_t)(b*8 + h) * TL) + t) * WN + w] = out;
    } else {
        int h = lc >> 6, d = lc & 63;
        *(float4*)&g_v[(((size_t)(b*8 + h) * TL) + t) * HD + d] = out;
    }
}

// ---------------- stage 2: attention, ONE causal tile per CTA --------------
// grid (16 bh, 36 tiles): tile id -> (qt, kti) triangular decode; 576 CTAs
__global__ __launch_bounds__(256, 2)
void attn_tile()
{
    __shared__ float s_fpa[64 * 52];
    __shared__ float s_s2p[64 * 4];
    __shared__ float s_att[64 * 68];
    __shared__ float s_v  [64 * 68];

    const int bh = blockIdx.x;
    // triangular decode: by -> (qt, kti), kti <= qt
    int by = blockIdx.y;
    int qt = (int)((sqrtf((float)(8 * by + 1)) - 1.0f) * 0.5f);
    int tri = (qt * (qt + 1)) >> 1;
    if (by < tri)               { qt--; tri = (qt * (qt + 1)) >> 1; }
    else if (by >= tri + qt + 1){ qt++; tri = (qt * (qt + 1)) >> 1; }
    const int kti = by - tri;
    const int kt  = kti * 64;

    const int tid = threadIdx.x;
    const int qa = tid >> 2;
    const int g  = tid & 3;
    const int ty = tid >> 4;
    const int tx = tid & 15;
    const int qglob = qt * 64 + qa;
    const int b = bh >> 3, h = bh & 7;

    // q-side params in packed registers
    u64 fq2[8], pq2[8], aq2[8];
    {
        const ulonglong2* f2 = (const ulonglong2*)(g_freq  + (((size_t)bh*TL) + qglob) * WN);
        const ulonglong2* p2 = (const ulonglong2*)(g_phase + (((size_t)bh*TL) + qglob) * WN);
        const ulonglong2* a2 = (const ulonglong2*)(g_amp   + (((size_t)bh*TL) + qglob) * WN);
#pragma unroll
        for (int i = 0; i < 4; i++) {
            ulonglong2 t;
            t = f2[i]; fq2[2*i] = t.x; fq2[2*i+1] = t.y;
            t = p2[i]; pq2[2*i] = t.x; pq2[2*i+1] = t.y;
            t = a2[i]; aq2[2*i] = t.x; aq2[2*i+1] = t.y;
        }
    }
    float s2q;
    {
        u64 s2 = 0ull;
#pragma unroll
        for (int i = 0; i < 8; i++) s2 = f2fma(aq2[i], aq2[i], s2);
        float lo, hi; up2(s2, lo, hi); s2q = lo + hi;
    }

    // ---- stage k-tile: negated f/p, amp, per-row a^2 partials, V ----
    {
        int row = tid >> 2, c4 = (tid & 3) << 2;
        size_t base = ((size_t)bh * TL + (kt + row)) * WN + c4;
        float4 f = *(const float4*)(g_freq  + base);
        float4 p = *(const float4*)(g_phase + base);
        float4 a = *(const float4*)(g_amp   + base);
        *(float4*)&s_fpa[row*52 +      c4] = make_float4(-f.x, -f.y, -f.z, -f.w);
        *(float4*)&s_fpa[row*52 + 16 + c4] = make_float4(-p.x, -p.y, -p.z, -p.w);
        *(float4*)&s_fpa[row*52 + 32 + c4] = a;
        s_s2p[row*4 + (tid & 3)] = a.x*a.x + a.y*a.y + a.z*a.z + a.w*a.w;
#pragma unroll
        for (int i = 0; i < 4; i++) {
            int l = tid + i * 256;
            int r = l >> 4, cc = (l & 15) << 2;
            *(float4*)&s_v[r*68 + cc] =
                *(const float4*)(g_v + ((size_t)bh*TL + (kt + r)) * HD + cc);
        }
    }
    __syncthreads();

    // ---- phase A: attn tile (f32x2 wave pairs; direct MUFU cos) ----
#pragma unroll 1
    for (int j = 0; j < 16; j++) {
        int kl = g + (j << 2);
        int kg = kt + kl;
        float attv = 0.f;
        if (kg <= qglob) {
            const float dtv = (float)(qglob - kg);
            const u64 dt2 = dup2(dtv);
            const float* fk = &s_fpa[kl * 52];
            float4 s2p = *(const float4*)&s_s2p[kl * 4];
            float s2k = (s2p.x + s2p.y) + (s2p.z + s2p.w);
            u64 cacc2 = 0ull, dacc2 = 0ull;
#pragma unroll
            for (int g4 = 0; g4 < 4; g4++) {
                ulonglong2 nf = *(const ulonglong2*)(fk +      (g4 << 2));
                ulonglong2 np = *(const ulonglong2*)(fk + 16 + (g4 << 2));
                ulonglong2 aa = *(const ulonglong2*)(fk + 32 + (g4 << 2));
#pragma unroll
                for (int half = 0; half < 2; half++) {
                    int wp = 2*g4 + half;
                    u64 nfp = half ? nf.y : nf.x;
                    u64 npp = half ? np.y : np.x;
                    u64 aap = half ? aa.y : aa.x;
                    u64 dw  = f2add(fq2[wp], nfp);
                    u64 dp  = f2add(pq2[wp], npp);
                    u64 arg = f2fma(dw, dt2, dp);
                    float r0, r1; up2(arg, r0, r1);
                    u64 cs  = pk2(__cosf(r0), __cosf(r1));
                    u64 pp  = f2mul(aq2[wp], aap);
                    dacc2 = f2add(dacc2, pp);
                    cacc2 = f2fma(pp, cs, cacc2);
                }
            }
            float c0, c1, d0, d1;
            up2(cacc2, c0, c1); up2(dacc2, d0, d1);
            float cacc = c0 + c1, dacc = d0 + d1;
            float S  = s2q + s2k;
            float it = fmaf(2.f, cacc, S);
            float en = fmaf(2.f, dacc, S) + 1e-8f;
            attv = __fdividef(it, en);
        }
        s_att[kl * 68 + qa] = attv;
    }
    __syncthreads();

    // ---- phase B: acc = attn_tile @ V_tile (f32x2) ----
    u64 acc2[4][2] = {};
#pragma unroll 4
    for (int kk = 0; kk < 64; kk++) {
        float4 a4 = *(const float4*)&s_att[kk*68 + (ty << 2)];
        ulonglong2 vv = *(const ulonglong2*)&s_v[kk*68 + (tx << 2)];
        mm4x4(a4, vv, acc2);
    }

    // ---- epilogue: write tile to slot kti ----
    float* dst = g_att8 + (size_t)kti * ATT_SZ;
#pragma unroll
    for (int i = 0; i < 4; i++) {
        float c0, c1, c2, c3;
        up2(acc2[i][0], c0, c1);
        up2(acc2[i][1], c2, c3);
        int row = qt * 64 + (ty << 2) + i;
        *(float4*)&dst[((size_t)(b * TL + row)) * DM + h * HD + (tx << 2)] =
            make_float4(c0, c1, c2, c3);
    }
}

// ---------------- stage 2b: reduce live slots 1..qt into slot 0 ------------
// grid 1024 rows, 128 threads (one float4 per thread across 512 cols)
__global__ __launch_bounds__(128)
void attred()
{
    const int m   = blockIdx.x;
    const int col = threadIdx.x * 4;
    const int nsum = ((m & 511) >> 6) + 1;       // live slots for this row
    const size_t off = (size_t)m * DM + col;

    ulonglong2 acc = *(const ulonglong2*)(g_att8 + off);
#pragma unroll
    for (int jb = 1; jb < 8; jb++) {
        if (jb < nsum) {
            ulonglong2 t = *(const ulonglong2*)(g_att8 + (size_t)jb * ATT_SZ + off);
            acc.x = f2add(acc.x, t.x);
            acc.y = f2add(acc.y, t.y);
        }
    }
    *(ulonglong2*)(g_att8 + off) = acc;
}

// ---------------- stage 3a: output projection, split-K=4, single-A ---------
// grid (8 n-tiles, 16 m-tiles, 4 z); K=128 each; A = g_att8 slot 0
__global__ __launch_bounds__(256, 3)
void outp_split4(const float* __restrict__ Wo)
{
    const int n0 = blockIdx.x * 64;
    const int m0 = blockIdx.y * 64;
    const int z  = blockIdx.z;
    u64 acc2[4][2] = {};
    gemm64k(g_att8, Wo, DM, m0, n0, z * 128, z * 128 + 128, acc2);

    float* dst = g_y4 + (size_t)z * Y_SZ;
    const int tx = threadIdx.x & 15, ty = threadIdx.x >> 4;
#pragma unroll
    for (int i = 0; i < 4; i++) {
        float c0, c1, c2, c3;
        up2(acc2[i][0], c0, c1);
        up2(acc2[i][1], c2, c3);
        int m = m0 + (ty << 2) + i;
        *(float4*)&dst[(size_t)m * DM + n0 + (tx << 2)] =
            make_float4(c0, c1, c2, c3);
    }
}

// ---------------- stage 3b: y = sum(4 partials) + bias ----------------------
__global__ __launch_bounds__(256)
void yred(const float* __restrict__ bo, float* __restrict__ y)
{
    int i = blockIdx.x * 256 + threadIdx.x;      // float4 index, 131072 total
    float4 p0 = ((const float4*)(g_y4 + 0*Y_SZ))[i];
    float4 p1 = ((const float4*)(g_y4 + 1*Y_SZ))[i];
    float4 p2 = ((const float4*)(g_y4 + 2*Y_SZ))[i];
    float4 p3 = ((const float4*)(g_y4 + 3*Y_SZ))[i];
    int col = (i << 2) & 511;
    float4 bb = *(const float4*)(bo + col);
    ((float4*)y)[i] = make_float4(
        ((p0.x + p1.x) + (p2.x + p3.x)) + bb.x,
        ((p0.y + p1.y) + (p2.y + p3.y)) + bb.y,
        ((p0.z + p1.z) + (p2.z + p3.z)) + bb.z,
        ((p0.w + p1.w) + (p2.w + p3.w)) + bb.w);
}

// ---------------- launch ----------------------------------------------------
extern "C" void kernel_launch(void* const* d_in, const int* in_sizes, int n_in,
                              void* d_out, int out_size)
{
    const float* x  = (const float*)d_in[0];
    const float* Wf = (const float*)d_in[1];
    const float* bf = (const float*)d_in[2];
    const float* Wp = (const float*)d_in[3];
    const float* bp = (const float*)d_in[4];
    const float* Wa = (const float*)d_in[5];
    const float* ba = (const float*)d_in[6];
    const float* Wv = (const float*)d_in[7];
    const float* bv = (const float*)d_in[8];
    const float* Wo = (const float*)d_in[9];
    const float* bo = (const float*)d_in[10];
    float* y = (float*)d_out;

    proj_split<<<dim3(14, 16, 2), 256>>>(x, Wf, Wp, Wa, Wv);
    projred<<<1024, 224>>>(bf, bp, ba, bv);
    attn_tile<<<dim3(16, 36), 256>>>();
    attred<<<1024, 128>>>();
    outp_split4<<<dim3(8, 16, 4), 256>>>(Wo);
    yred<<<512, 256>>>(bo, y);
}